// round 13
// baseline (speedup 1.0000x reference)
#include <cuda_runtime.h>
#include <math.h>

// Problem constants
#define BB 4096
#define FF 2048
#define TT 16
#define KK 8
#define FT 64                 // f-tile staged in shared
#define NTILES (FF / FT)      // 32

// Reorganized W: [f][j][t] where entry = (W[2j,t,f], W[2j+1,t,f]) packed as float2.
// 2048 * 4 * 16 float2 = 1 MB static device scratch (allowed).
__device__ float2 g_Wr[FF * 4 * TT];

// ---------------------------------------------------------------------------
// Kernel 0: reorganize W [K,T,F] -> g_Wr [F][4][16] (k-pairs packed in float2)
// ---------------------------------------------------------------------------
__global__ void reorg_W_kernel(const float* __restrict__ W) {
    int tid = blockIdx.x * blockDim.x + threadIdx.x;   // 0 .. 131071
    int f = tid >> 6;
    int j = (tid >> 4) & 3;
    int t = tid & 15;
    float lo = W[(2 * j)     * TT * FF + t * FF + f];
    float hi = W[(2 * j + 1) * TT * FF + t * FF + f];
    g_Wr[tid] = make_float2(lo, hi);                   // index = f*64 + j*16 + t
}

// ---------------------------------------------------------------------------
// Packed fp32x2 helpers (Blackwell fma.rn.f32x2)
// ---------------------------------------------------------------------------
__device__ __forceinline__ unsigned long long pack2(float x) {
    unsigned long long r;
    asm("mov.b64 %0, {%1, %1};" : "=l"(r) : "r"(__float_as_uint(x)));
    return r;
}
__device__ __forceinline__ void ffma2(unsigned long long& acc,
                                      unsigned long long a,
                                      unsigned long long w) {
    asm("fma.rn.f32x2 %0, %1, %2, %0;" : "+l"(acc) : "l"(a), "l"(w));
}
__device__ __forceinline__ float sigmoidf_(float x) {
    return 1.0f / (1.0f + expf(-x));
}

// ---------------------------------------------------------------------------
// Main kernel: 256 threads/block, block covers 32 b-rows.
// thread: t = tid&15, bsub = tid>>4; handles b rows (base+bsub, base+16+bsub).
// acc layout: 4 x b64, each holding fp32 pair for k = (2j, 2j+1).
// ---------------------------------------------------------------------------
__global__ __launch_bounds__(256, 1)
void temporal_logits_kernel(const float* __restrict__ h,
                            const float* __restrict__ bias,
                            float* __restrict__ out) {
    __shared__ float2 ws[FT * 64];   // 32 KB: [fl][j][t]

    const int tid  = threadIdx.x;
    const int t    = tid & 15;
    const int bsub = tid >> 4;
    const int base = blockIdx.x * 32;
    const int bA   = base + bsub;
    const int bB   = base + 16 + bsub;

    const float* hA = h + (size_t)bA * (FF * TT) + t;
    const float* hB = h + (size_t)bB * (FF * TT) + t;

    const float4* wr4 = reinterpret_cast<const float4*>(g_Wr);
    float4* ws4       = reinterpret_cast<float4*>(ws);
    const unsigned long long* wsq =
        reinterpret_cast<const unsigned long long*>(ws);

    unsigned long long accA[4] = {0ull, 0ull, 0ull, 0ull};  // bits(0,0) = (0.f,0.f)
    unsigned long long accB[4] = {0ull, 0ull, 0ull, 0ull};

    // Stage tile 0 (32 KB = 2048 float4; 256 threads * 8)
#pragma unroll
    for (int i = 0; i < 8; i++) ws4[tid + 256 * i] = wr4[tid + 256 * i];
    __syncthreads();

    for (int tile = 0; tile < NTILES; tile++) {
        // Register-prefetch next tile (overlaps with the FMA loop below)
        float4 pf[8];
        if (tile + 1 < NTILES) {
            const float4* src = wr4 + (size_t)(tile + 1) * 2048;
#pragma unroll
            for (int i = 0; i < 8; i++) pf[i] = src[tid + 256 * i];
        }

        const float* pA = hA + (size_t)tile * FT * TT;
        const float* pB = hB + (size_t)tile * FT * TT;

#pragma unroll 16
        for (int fl = 0; fl < FT; fl++) {
            unsigned long long aa = pack2(__ldg(pA + fl * TT));
            unsigned long long cc = pack2(__ldg(pB + fl * TT));
            unsigned long long w0 = wsq[fl * 64 + t];
            unsigned long long w1 = wsq[fl * 64 + 16 + t];
            unsigned long long w2 = wsq[fl * 64 + 32 + t];
            unsigned long long w3 = wsq[fl * 64 + 48 + t];
            ffma2(accA[0], aa, w0);
            ffma2(accA[1], aa, w1);
            ffma2(accA[2], aa, w2);
            ffma2(accA[3], aa, w3);
            ffma2(accB[0], cc, w0);
            ffma2(accB[1], cc, w1);
            ffma2(accB[2], cc, w2);
            ffma2(accB[3], cc, w3);
        }

        __syncthreads();
        if (tile + 1 < NTILES) {
#pragma unroll
            for (int i = 0; i < 8; i++) ws4[tid + 256 * i] = pf[i];
        }
        __syncthreads();
    }

    // Epilogue: bias + sigmoid + store [B,T,K]
    float bs[KK];
#pragma unroll
    for (int k = 0; k < KK; k++) bs[k] = __ldg(bias + k * TT + t);

    float la[KK], lb[KK];
#pragma unroll
    for (int j = 0; j < 4; j++) {
        float2 pa = *reinterpret_cast<float2*>(&accA[j]);
        float2 pb = *reinterpret_cast<float2*>(&accB[j]);
        la[2 * j] = pa.x; la[2 * j + 1] = pa.y;
        lb[2 * j] = pb.x; lb[2 * j + 1] = pb.y;
    }

    float4* outA = reinterpret_cast<float4*>(out + ((size_t)bA * TT + t) * KK);
    float4* outB = reinterpret_cast<float4*>(out + ((size_t)bB * TT + t) * KK);
    outA[0] = make_float4(sigmoidf_(la[0] + bs[0]), sigmoidf_(la[1] + bs[1]),
                          sigmoidf_(la[2] + bs[2]), sigmoidf_(la[3] + bs[3]));
    outA[1] = make_float4(sigmoidf_(la[4] + bs[4]), sigmoidf_(la[5] + bs[5]),
                          sigmoidf_(la[6] + bs[6]), sigmoidf_(la[7] + bs[7]));
    outB[0] = make_float4(sigmoidf_(lb[0] + bs[0]), sigmoidf_(lb[1] + bs[1]),
                          sigmoidf_(lb[2] + bs[2]), sigmoidf_(lb[3] + bs[3]));
    outB[1] = make_float4(sigmoidf_(lb[4] + bs[4]), sigmoidf_(lb[5] + bs[5]),
                          sigmoidf_(lb[6] + bs[6]), sigmoidf_(lb[7] + bs[7]));
}

// ---------------------------------------------------------------------------
// Launch: reorg W once per replay (deterministic, ~2 us), then main kernel.
// Inputs (metadata order): h_ens [B,F,T] f32, W [K,T,F] f32, b [K,T] f32.
// Output: [B,T,K] f32.
// ---------------------------------------------------------------------------
extern "C" void kernel_launch(void* const* d_in, const int* in_sizes, int n_in,
                              void* d_out, int out_size) {
    const float* h    = (const float*)d_in[0];
    const float* W    = (const float*)d_in[1];
    const float* bias = (const float*)d_in[2];
    float* out        = (float*)d_out;

    // 131072 elements of g_Wr
    reorg_W_kernel<<<512, 256>>>(W);

    // 4096 b-rows / 32 per block = 128 blocks
    temporal_logits_kernel<<<BB / 32, 256>>>(h, bias, out);
}

// round 14
// speedup vs baseline: 1.2112x; 1.2112x over previous
#include <cuda_runtime.h>
#include <math.h>

// Problem constants
#define BB 4096
#define FF 2048
#define TT 16
#define KK 8
#define FT 32                 // f-tile per stage (16 KB)
#define FHALF (FF / 2)        // 1024 f per block
#define NTILES (FHALF / FT)   // 32 tiles per block

// Reorganized W: [f][j][t], entry = (W[2j,t,f], W[2j+1,t,f]) as float2. 1 MB.
__device__ float2 g_Wr[FF * 4 * TT];
// Partial logits per f-half, laid out exactly like out [B,T,K] (float4 quads). 4 MB.
__device__ float4 g_part[2][BB * TT * KK / 4];

// ---------------------------------------------------------------------------
// Kernel 0: reorganize W [K,T,F] -> g_Wr [F][4][16]
// ---------------------------------------------------------------------------
__global__ void reorg_W_kernel(const float* __restrict__ W) {
    int tid = blockIdx.x * blockDim.x + threadIdx.x;   // 0 .. 131071
    int f = tid >> 6;
    int j = (tid >> 4) & 3;
    int t = tid & 15;
    float lo = W[(2 * j)     * TT * FF + t * FF + f];
    float hi = W[(2 * j + 1) * TT * FF + t * FF + f];
    g_Wr[tid] = make_float2(lo, hi);                   // idx = f*64 + j*16 + t
}

// ---------------------------------------------------------------------------
// Helpers
// ---------------------------------------------------------------------------
__device__ __forceinline__ unsigned long long pack2(float x) {
    unsigned long long r;
    asm("mov.b64 %0, {%1, %1};" : "=l"(r) : "r"(__float_as_uint(x)));
    return r;
}
__device__ __forceinline__ void ffma2(unsigned long long& acc,
                                      unsigned long long a,
                                      unsigned long long w) {
    asm("fma.rn.f32x2 %0, %1, %2, %0;" : "+l"(acc) : "l"(a), "l"(w));
}
__device__ __forceinline__ void cpa16(void* dst_smem, const void* src) {
    unsigned s = (unsigned)__cvta_generic_to_shared(dst_smem);
    asm volatile("cp.async.cg.shared.global [%0], [%1], 16;" :: "r"(s), "l"(src));
}
__device__ __forceinline__ void cp_commit() {
    asm volatile("cp.async.commit_group;");
}
__device__ __forceinline__ float sigmoidf_(float x) {
    return 1.0f / (1.0f + expf(-x));
}

// ---------------------------------------------------------------------------
// Main kernel: 256 blocks (128 b-blocks x 2 f-halves), 256 threads.
// thread: t = tid&15, bsub = tid>>4; rows (base+bsub, base+16+bsub).
// Writes partial logits (no bias/sigmoid) to g_part[f_half].
// ---------------------------------------------------------------------------
__global__ __launch_bounds__(256, 2)
void temporal_partial_kernel(const float* __restrict__ h) {
    __shared__ float4 buf[2][FT * 32];   // 2 x 16 KB double buffer

    const int tid  = threadIdx.x;
    const int t    = tid & 15;
    const int bsub = tid >> 4;
    const int bblk = blockIdx.x & 127;
    const int yh   = blockIdx.x >> 7;      // f-half

    const int bA = bblk * 32 + bsub;
    const int bB = bA + 16;

    const float* hA = h + (size_t)bA * (FF * TT) + (size_t)yh * FHALF * TT + t;
    const float* hB = h + (size_t)bB * (FF * TT) + (size_t)yh * FHALF * TT + t;

    // W source for this f-half, in float4 units (f*32 float4 per f... 32/f)
    const float4* wsrc = reinterpret_cast<const float4*>(g_Wr)
                         + (size_t)yh * FHALF * 32;

    unsigned long long accA[4] = {0ull, 0ull, 0ull, 0ull};
    unsigned long long accB[4] = {0ull, 0ull, 0ull, 0ull};

    // Prologue: stage tiles 0 and 1 (each 1024 float4; 256 thr x 4)
#pragma unroll
    for (int j = 0; j < 4; j++)
        cpa16(&buf[0][tid + 256 * j], wsrc + tid + 256 * j);
    cp_commit();
#pragma unroll
    for (int j = 0; j < 4; j++)
        cpa16(&buf[1][tid + 256 * j], wsrc + 1024 + tid + 256 * j);
    cp_commit();

    for (int tile = 0; tile < NTILES; tile++) {
        if (tile < NTILES - 1) {
            asm volatile("cp.async.wait_group 1;");
        } else {
            asm volatile("cp.async.wait_group 0;");
        }
        __syncthreads();

        const unsigned long long* wq =
            reinterpret_cast<const unsigned long long*>(buf[tile & 1]);
        const float* pA = hA + (size_t)tile * FT * TT;
        const float* pB = hB + (size_t)tile * FT * TT;

#pragma unroll
        for (int fl = 0; fl < FT; fl++) {
            unsigned long long aa = pack2(__ldg(pA + fl * TT));
            unsigned long long cc = pack2(__ldg(pB + fl * TT));
            unsigned long long w0 = wq[fl * 64 + t];
            unsigned long long w1 = wq[fl * 64 + 16 + t];
            unsigned long long w2 = wq[fl * 64 + 32 + t];
            unsigned long long w3 = wq[fl * 64 + 48 + t];
            ffma2(accA[0], aa, w0);
            ffma2(accA[1], aa, w1);
            ffma2(accA[2], aa, w2);
            ffma2(accA[3], aa, w3);
            ffma2(accB[0], cc, w0);
            ffma2(accB[1], cc, w1);
            ffma2(accB[2], cc, w2);
            ffma2(accB[3], cc, w3);
        }

        __syncthreads();
        if (tile + 2 < NTILES) {
            const float4* src = wsrc + (size_t)(tile + 2) * 1024;
#pragma unroll
            for (int j = 0; j < 4; j++)
                cpa16(&buf[tile & 1][tid + 256 * j], src + tid + 256 * j);
            cp_commit();
        }
    }

    // Write partials: two float4 per row, layout [B,T,K]
    float2* a = reinterpret_cast<float2*>(accA);
    float2* c = reinterpret_cast<float2*>(accB);
    float4* dstA = &g_part[yh][(size_t)(bA * TT + t) * 2];
    float4* dstB = &g_part[yh][(size_t)(bB * TT + t) * 2];
    dstA[0] = make_float4(a[0].x, a[0].y, a[1].x, a[1].y);
    dstA[1] = make_float4(a[2].x, a[2].y, a[3].x, a[3].y);
    dstB[0] = make_float4(c[0].x, c[0].y, c[1].x, c[1].y);
    dstB[1] = make_float4(c[2].x, c[2].y, c[3].x, c[3].y);
}

// ---------------------------------------------------------------------------
// Combine: out = sigmoid(part0 + part1 + bias), float4 per thread.
// ---------------------------------------------------------------------------
__global__ void combine_kernel(const float* __restrict__ bias,
                               float4* __restrict__ out) {
    int u = blockIdx.x * blockDim.x + threadIdx.x;   // 0 .. 131071
    float4 p0 = g_part[0][u];
    float4 p1 = g_part[1][u];
    int half = u & 1;
    int t = (u >> 1) & 15;
    int k0 = half * 4;
    float4 r;
    r.x = sigmoidf_(p0.x + p1.x + __ldg(bias + (k0 + 0) * TT + t));
    r.y = sigmoidf_(p0.y + p1.y + __ldg(bias + (k0 + 1) * TT + t));
    r.z = sigmoidf_(p0.z + p1.z + __ldg(bias + (k0 + 2) * TT + t));
    r.w = sigmoidf_(p0.w + p1.w + __ldg(bias + (k0 + 3) * TT + t));
    out[u] = r;
}

// ---------------------------------------------------------------------------
// Launch. Inputs: h_ens [B,F,T] f32, W [K,T,F] f32, b [K,T] f32. Out [B,T,K].
// ---------------------------------------------------------------------------
extern "C" void kernel_launch(void* const* d_in, const int* in_sizes, int n_in,
                              void* d_out, int out_size) {
    const float* h    = (const float*)d_in[0];
    const float* W    = (const float*)d_in[1];
    const float* bias = (const float*)d_in[2];
    float4* out       = (float4*)d_out;

    reorg_W_kernel<<<512, 256>>>(W);
    temporal_partial_kernel<<<256, 256>>>(h);
    combine_kernel<<<512, 256>>>(bias, out);
}

// round 15
// speedup vs baseline: 1.2140x; 1.0023x over previous
#include <cuda_runtime.h>
#include <math.h>

// Problem constants
#define BB 4096
#define FF 2048
#define TT 16
#define KK 8
#define FT 32                 // f-tile per stage (16 KB)
#define FHALF (FF / 2)        // 1024 f per block
#define NTILES (FHALF / FT)   // 32 tiles per block

// Reorganized W: [f][j][t], entry = (W[2j,t,f], W[2j+1,t,f]) as float2. 1 MB.
__device__ float2 g_Wr[FF * 4 * TT];
// Partial logits per f-half, laid out exactly like out [B,T,K] (float4 quads). 4 MB.
__device__ float4 g_part[2][BB * TT * KK / 4];

// ---------------------------------------------------------------------------
// Kernel 0: reorganize W [K,T,F] -> g_Wr [F][4][16]
// ---------------------------------------------------------------------------
__global__ void reorg_W_kernel(const float* __restrict__ W) {
    int tid = blockIdx.x * blockDim.x + threadIdx.x;   // 0 .. 131071
    int f = tid >> 6;
    int j = (tid >> 4) & 3;
    int t = tid & 15;
    float lo = W[(2 * j)     * TT * FF + t * FF + f];
    float hi = W[(2 * j + 1) * TT * FF + t * FF + f];
    g_Wr[tid] = make_float2(lo, hi);                   // idx = f*64 + j*16 + t
}

// ---------------------------------------------------------------------------
// Helpers
// ---------------------------------------------------------------------------
__device__ __forceinline__ unsigned long long pack2(float x) {
    unsigned long long r;
    asm("mov.b64 %0, {%1, %1};" : "=l"(r) : "r"(__float_as_uint(x)));
    return r;
}
__device__ __forceinline__ void ffma2(unsigned long long& acc,
                                      unsigned long long a,
                                      unsigned long long w) {
    asm("fma.rn.f32x2 %0, %1, %2, %0;" : "+l"(acc) : "l"(a), "l"(w));
}
__device__ __forceinline__ void cpa16(void* dst_smem, const void* src) {
    unsigned s = (unsigned)__cvta_generic_to_shared(dst_smem);
    asm volatile("cp.async.cg.shared.global [%0], [%1], 16;" :: "r"(s), "l"(src));
}
__device__ __forceinline__ void cp_commit() {
    asm volatile("cp.async.commit_group;");
}
__device__ __forceinline__ float sigmoidf_(float x) {
    return 1.0f / (1.0f + expf(-x));
}

// ---------------------------------------------------------------------------
// Main kernel: 256 blocks (128 b-blocks x 2 f-halves), 256 threads.
// thread: t = tid&15, bsub = tid>>4; rows (base+bsub, base+16+bsub).
// Writes partial logits (no bias/sigmoid) to g_part[f_half].
// ---------------------------------------------------------------------------
__global__ __launch_bounds__(256, 2)
void temporal_partial_kernel(const float* __restrict__ h) {
    __shared__ float4 buf[2][FT * 32];   // 2 x 16 KB double buffer

    const int tid  = threadIdx.x;
    const int t    = tid & 15;
    const int bsub = tid >> 4;
    const int bblk = blockIdx.x & 127;
    const int yh   = blockIdx.x >> 7;      // f-half

    const int bA = bblk * 32 + bsub;
    const int bB = bA + 16;

    const float* hA = h + (size_t)bA * (FF * TT) + (size_t)yh * FHALF * TT + t;
    const float* hB = h + (size_t)bB * (FF * TT) + (size_t)yh * FHALF * TT + t;

    // W source for this f-half, in float4 units (f*32 float4 per f... 32/f)
    const float4* wsrc = reinterpret_cast<const float4*>(g_Wr)
                         + (size_t)yh * FHALF * 32;

    unsigned long long accA[4] = {0ull, 0ull, 0ull, 0ull};
    unsigned long long accB[4] = {0ull, 0ull, 0ull, 0ull};

    // Prologue: stage tiles 0 and 1 (each 1024 float4; 256 thr x 4)
#pragma unroll
    for (int j = 0; j < 4; j++)
        cpa16(&buf[0][tid + 256 * j], wsrc + tid + 256 * j);
    cp_commit();
#pragma unroll
    for (int j = 0; j < 4; j++)
        cpa16(&buf[1][tid + 256 * j], wsrc + 1024 + tid + 256 * j);
    cp_commit();

    for (int tile = 0; tile < NTILES; tile++) {
        if (tile < NTILES - 1) {
            asm volatile("cp.async.wait_group 1;");
        } else {
            asm volatile("cp.async.wait_group 0;");
        }
        __syncthreads();

        const unsigned long long* wq =
            reinterpret_cast<const unsigned long long*>(buf[tile & 1]);
        const float* pA = hA + (size_t)tile * FT * TT;
        const float* pB = hB + (size_t)tile * FT * TT;

#pragma unroll
        for (int fl = 0; fl < FT; fl++) {
            unsigned long long aa = pack2(__ldg(pA + fl * TT));
            unsigned long long cc = pack2(__ldg(pB + fl * TT));
            unsigned long long w0 = wq[fl * 64 + t];
            unsigned long long w1 = wq[fl * 64 + 16 + t];
            unsigned long long w2 = wq[fl * 64 + 32 + t];
            unsigned long long w3 = wq[fl * 64 + 48 + t];
            ffma2(accA[0], aa, w0);
            ffma2(accA[1], aa, w1);
            ffma2(accA[2], aa, w2);
            ffma2(accA[3], aa, w3);
            ffma2(accB[0], cc, w0);
            ffma2(accB[1], cc, w1);
            ffma2(accB[2], cc, w2);
            ffma2(accB[3], cc, w3);
        }

        __syncthreads();
        if (tile + 2 < NTILES) {
            const float4* src = wsrc + (size_t)(tile + 2) * 1024;
#pragma unroll
            for (int j = 0; j < 4; j++)
                cpa16(&buf[tile & 1][tid + 256 * j], src + tid + 256 * j);
            cp_commit();
        }
    }

    // Write partials: two float4 per row, layout [B,T,K]
    float2* a = reinterpret_cast<float2*>(accA);
    float2* c = reinterpret_cast<float2*>(accB);
    float4* dstA = &g_part[yh][(size_t)(bA * TT + t) * 2];
    float4* dstB = &g_part[yh][(size_t)(bB * TT + t) * 2];
    dstA[0] = make_float4(a[0].x, a[0].y, a[1].x, a[1].y);
    dstA[1] = make_float4(a[2].x, a[2].y, a[3].x, a[3].y);
    dstB[0] = make_float4(c[0].x, c[0].y, c[1].x, c[1].y);
    dstB[1] = make_float4(c[2].x, c[2].y, c[3].x, c[3].y);
}

// ---------------------------------------------------------------------------
// Combine: out = sigmoid(part0 + part1 + bias), float4 per thread.
// ---------------------------------------------------------------------------
__global__ void combine_kernel(const float* __restrict__ bias,
                               float4* __restrict__ out) {
    int u = blockIdx.x * blockDim.x + threadIdx.x;   // 0 .. 131071
    float4 p0 = g_part[0][u];
    float4 p1 = g_part[1][u];
    int half = u & 1;
    int t = (u >> 1) & 15;
    int k0 = half * 4;
    float4 r;
    r.x = sigmoidf_(p0.x + p1.x + __ldg(bias + (k0 + 0) * TT + t));
    r.y = sigmoidf_(p0.y + p1.y + __ldg(bias + (k0 + 1) * TT + t));
    r.z = sigmoidf_(p0.z + p1.z + __ldg(bias + (k0 + 2) * TT + t));
    r.w = sigmoidf_(p0.w + p1.w + __ldg(bias + (k0 + 3) * TT + t));
    out[u] = r;
}

// ---------------------------------------------------------------------------
// Launch. Inputs: h_ens [B,F,T] f32, W [K,T,F] f32, b [K,T] f32. Out [B,T,K].
// ---------------------------------------------------------------------------
extern "C" void kernel_launch(void* const* d_in, const int* in_sizes, int n_in,
                              void* d_out, int out_size) {
    const float* h    = (const float*)d_in[0];
    const float* W    = (const float*)d_in[1];
    const float* bias = (const float*)d_in[2];
    float4* out       = (float4*)d_out;

    reorg_W_kernel<<<512, 256>>>(W);
    temporal_partial_kernel<<<256, 256>>>(h);
    combine_kernel<<<512, 256>>>(bias, out);
}